// round 1
// baseline (speedup 1.0000x reference)
#include <cuda_runtime.h>
#include <cstdint>

// Problem constants (fixed by the benchmark instance)
#define B_    32
#define CIN   256
#define COUT  512
#define HIN   56
#define WIN   56
#define HOUT  54
#define WOUT  54
#define HWOUT (HOUT * WOUT)          // 2916
#define EPS   1e-5f
#define DW_THRESH 4.0f
#define PW_THRESH 0.001f

// Scratch: depthwise output (only written for surviving maps) + survival flags.
// Device globals are the allowed scratch mechanism (no allocations permitted).
__device__ float g_y[(size_t)B_ * CIN * HWOUT];   // ~95.5 MB
__device__ int   g_flag[B_ * CIN];

__device__ __forceinline__ float block_max_256(float v) {
    __shared__ float s_red[8];
    #pragma unroll
    for (int off = 16; off > 0; off >>= 1)
        v = fmaxf(v, __shfl_down_sync(0xffffffffu, v, off));
    if ((threadIdx.x & 31) == 0) s_red[threadIdx.x >> 5] = v;
    __syncthreads();
    if (threadIdx.x < 8) {
        v = s_red[threadIdx.x];
        #pragma unroll
        for (int off = 4; off > 0; off >>= 1)
            v = fmaxf(v, __shfl_down_sync(0xffu, v, off));
        if (threadIdx.x == 0) s_red[0] = v;
    }
    __syncthreads();
    float r = s_red[0];
    __syncthreads();   // protect s_red reuse across calls
    return r;
}

// ---------------------------------------------------------------------------
// Kernel A: depthwise 3x3 VALID conv + bias + BN + ReLU + map-max + cut flag.
// One block (256 threads) per (batch, channel) map. Writes y only if the map
// survives the DW_THRESH cut; always writes the flag.
// ---------------------------------------------------------------------------
__global__ __launch_bounds__(256, 8)
void dw_kernel(const float* __restrict__ x,
               const float* __restrict__ dw_w,
               const float* __restrict__ dw_b,
               const float* __restrict__ dw_gamma,
               const float* __restrict__ dw_beta,
               const float* __restrict__ dw_mean,
               const float* __restrict__ dw_var)
{
    const int map = blockIdx.x;            // b * CIN + c
    const int c   = map & (CIN - 1);
    const int tid = threadIdx.x;

    __shared__ float tile[HIN * WIN];      // 56*56 floats = 12.25 KB
    __shared__ float wk[9];

    const float* xin = x + (size_t)map * (HIN * WIN);
    #pragma unroll 4
    for (int i = tid; i < HIN * WIN; i += 256) tile[i] = xin[i];
    if (tid < 9) wk[tid] = dw_w[c * 9 + tid];
    __syncthreads();

    const float scale = dw_gamma[c] * rsqrtf(dw_var[c] + EPS);
    const float shift = dw_beta[c] - dw_mean[c] * scale;
    const float bias  = dw_b[c];

    float vals[12];
    float mx = 0.0f;

    #pragma unroll
    for (int r = 0; r < 12; r++) {
        const int idx = tid + r * 256;
        float v = 0.0f;
        if (idx < HWOUT) {
            const int oh = idx / WOUT;
            const int ow = idx - oh * WOUT;
            const float* p = tile + oh * WIN + ow;
            float acc;
            acc = p[0]          * wk[0];
            acc = fmaf(p[1],           wk[1], acc);
            acc = fmaf(p[2],           wk[2], acc);
            acc = fmaf(p[WIN + 0],     wk[3], acc);
            acc = fmaf(p[WIN + 1],     wk[4], acc);
            acc = fmaf(p[WIN + 2],     wk[5], acc);
            acc = fmaf(p[2*WIN + 0],   wk[6], acc);
            acc = fmaf(p[2*WIN + 1],   wk[7], acc);
            acc = fmaf(p[2*WIN + 2],   wk[8], acc);
            v = fmaf(acc + bias, scale, shift - scale * 0.0f); // (acc+bias)*scale + shift
            v = fmaxf((acc + bias) * scale + shift, 0.0f);
        }
        vals[r] = v;
        mx = fmaxf(mx, fabsf(v));
    }

    const float bmax = block_max_256(mx);
    const int survive = (bmax >= DW_THRESH) ? 1 : 0;
    if (tid == 0) g_flag[map] = survive;

    if (survive) {
        float* yout = g_y + (size_t)map * HWOUT;
        #pragma unroll
        for (int r = 0; r < 12; r++) {
            const int idx = tid + r * 256;
            if (idx < HWOUT) yout[idx] = vals[r];
        }
    }
}

// ---------------------------------------------------------------------------
// Kernel B: pointwise 1x1 conv (channel GEMM over surviving channels only)
// + bias + BN + ReLU + map-max + cut, then final store.
// One block (256 threads) per (batch, out-channel) map.
// ---------------------------------------------------------------------------
__global__ __launch_bounds__(256, 8)
void pw_kernel(const float* __restrict__ pw_w,
               const float* __restrict__ pw_b,
               const float* __restrict__ pw_gamma,
               const float* __restrict__ pw_beta,
               const float* __restrict__ pw_mean,
               const float* __restrict__ pw_var,
               float* __restrict__ out)
{
    const int bo = blockIdx.x;             // b * COUT + o
    const int o  = bo & (COUT - 1);
    const int bi = bo >> 9;                // COUT = 512
    const int tid = threadIdx.x;

    __shared__ float wrow[CIN];
    __shared__ int   flg[CIN];
    wrow[tid]        = pw_w[(size_t)o * CIN + tid];
    flg[tid]         = g_flag[bi * CIN + tid];
    __syncthreads();

    float acc[12];
    #pragma unroll
    for (int r = 0; r < 12; r++) acc[r] = 0.0f;

    // Deterministic ascending-channel accumulation; dead channels skipped
    // without touching their y maps (which were never written).
    for (int k = 0; k < CIN; k++) {
        if (!flg[k]) continue;
        const float wv = wrow[k];
        const float* yr = g_y + ((size_t)bi * CIN + k) * HWOUT;
        #pragma unroll
        for (int r = 0; r < 12; r++) {
            const int idx = tid + r * 256;
            if (idx < HWOUT) acc[r] = fmaf(yr[idx], wv, acc[r]);
        }
    }

    const float scale = pw_gamma[o] * rsqrtf(pw_var[o] + EPS);
    const float shift = pw_beta[o] - pw_mean[o] * scale;
    const float bias  = pw_b[o];

    float z[12];
    float mx = 0.0f;
    #pragma unroll
    for (int r = 0; r < 12; r++) {
        float v = fmaxf((acc[r] + bias) * scale + shift, 0.0f);
        z[r] = v;
        mx = fmaxf(mx, fabsf(v));
    }

    const float bmax = block_max_256(mx);
    const bool cut = (bmax < PW_THRESH);

    float* op = out + (size_t)bo * HWOUT;
    #pragma unroll
    for (int r = 0; r < 12; r++) {
        const int idx = tid + r * 256;
        if (idx < HWOUT) op[idx] = cut ? 0.0f : z[r];
    }
}

// ---------------------------------------------------------------------------
// Launch
// ---------------------------------------------------------------------------
extern "C" void kernel_launch(void* const* d_in, const int* in_sizes, int n_in,
                              void* d_out, int out_size)
{
    const float* x        = (const float*)d_in[0];
    const float* dw_w     = (const float*)d_in[1];
    const float* dw_b     = (const float*)d_in[2];
    const float* dw_gamma = (const float*)d_in[3];
    const float* dw_beta  = (const float*)d_in[4];
    const float* dw_mean  = (const float*)d_in[5];
    const float* dw_var   = (const float*)d_in[6];
    const float* pw_w     = (const float*)d_in[7];
    const float* pw_b     = (const float*)d_in[8];
    const float* pw_gamma = (const float*)d_in[9];
    const float* pw_beta  = (const float*)d_in[10];
    const float* pw_mean  = (const float*)d_in[11];
    const float* pw_var   = (const float*)d_in[12];
    float* out = (float*)d_out;

    dw_kernel<<<B_ * CIN, 256>>>(x, dw_w, dw_b, dw_gamma, dw_beta, dw_mean, dw_var);
    pw_kernel<<<B_ * COUT, 256>>>(pw_w, pw_b, pw_gamma, pw_beta, pw_mean, pw_var, out);
}

// round 2
// speedup vs baseline: 5.5189x; 5.5189x over previous
#include <cuda_runtime.h>
#include <cstdint>

#define B_    32
#define CIN   256
#define COUT  512
#define HIN   56
#define WIN   56
#define HOUT  54
#define WOUT  54
#define HWOUT (HOUT * WOUT)          // 2916 = 729 * 4
#define EPS   1e-5f
#define DW_THRESH 4.0f
#define PW_THRESH 0.001f

// Scratch (device globals: the only allowed scratch mechanism).
__device__ float g_y[(size_t)B_ * CIN * HWOUT];   // depthwise output, written only for survivors
__device__ int   g_flag[B_ * CIN];                // per-(b,c) survival flag
__device__ int   g_cnt[B_];                       // survivors per batch
__device__ short g_list[B_ * CIN];                // compacted ascending channel list per batch

__device__ __forceinline__ float block_max_256(float v) {
    __shared__ float s_red[8];
    #pragma unroll
    for (int off = 16; off > 0; off >>= 1)
        v = fmaxf(v, __shfl_down_sync(0xffffffffu, v, off));
    if ((threadIdx.x & 31) == 0) s_red[threadIdx.x >> 5] = v;
    __syncthreads();
    if (threadIdx.x < 8) {
        v = s_red[threadIdx.x];
        #pragma unroll
        for (int off = 4; off > 0; off >>= 1)
            v = fmaxf(v, __shfl_down_sync(0xffu, v, off));
        if (threadIdx.x == 0) s_red[0] = v;
    }
    __syncthreads();
    float r = s_red[0];
    __syncthreads();
    return r;
}

// ---------------------------------------------------------------------------
// Kernel A: depthwise 3x3 VALID + bias + BN + ReLU + map-max + cut flag.
// One 256-thread block per (b,c) map. Column-strip layout: each thread owns a
// fixed column and 14 output rows with a rolling 3x3 register window.
// ---------------------------------------------------------------------------
__global__ __launch_bounds__(256, 8)
void dw_kernel(const float* __restrict__ x,
               const float* __restrict__ dw_w,
               const float* __restrict__ dw_b,
               const float* __restrict__ dw_gamma,
               const float* __restrict__ dw_beta,
               const float* __restrict__ dw_mean,
               const float* __restrict__ dw_var)
{
    const int map = blockIdx.x;            // b * CIN + c
    const int c   = map & (CIN - 1);
    const int tid = threadIdx.x;

    __shared__ float tile[HIN * WIN];      // 12.25 KB
    __shared__ float wsh[9];

    // Vectorized tile load: 3136 floats = 784 float4
    {
        const float4* xin4 = (const float4*)(x + (size_t)map * (HIN * WIN));
        float4* t4 = (float4*)tile;
        #pragma unroll
        for (int r = 0; r < 4; r++) {
            const int i = tid + r * 256;
            if (i < (HIN * WIN) / 4) t4[i] = xin4[i];
        }
    }
    if (tid < 9) wsh[tid] = dw_w[c * 9 + tid];
    __syncthreads();

    const float w0 = wsh[0], w1 = wsh[1], w2 = wsh[2];
    const float w3 = wsh[3], w4 = wsh[4], w5 = wsh[5];
    const float w6 = wsh[6], w7 = wsh[7], w8 = wsh[8];

    const float scale = dw_gamma[c] * rsqrtf(dw_var[c] + EPS);
    const float shift = dw_beta[c] - dw_mean[c] * scale;
    const float bias  = dw_b[c];

    const int col   = tid & 63;            // 0..63 (valid < 54)
    const int grp   = tid >> 6;            // 0..3
    const int row0  = grp * 14;            // output rows [row0, row0+nrows)
    const int nrows = (grp == 3) ? (HOUT - 42) : 14;   // 14,14,14,12
    const bool colok = (col < WOUT);

    float vals[14];
    float mx = 0.0f;

    if (colok) {
        const float* p = tile + row0 * WIN + col;
        float a0 = p[0], a1 = p[1], a2 = p[2]; p += WIN;
        float b0 = p[0], b1 = p[1], b2 = p[2]; p += WIN;
        #pragma unroll
        for (int r = 0; r < 14; r++) {
            if (r < nrows) {
                const float c0 = p[0], c1 = p[1], c2 = p[2]; p += WIN;
                float acc = a0 * w0;
                acc = fmaf(a1, w1, acc);
                acc = fmaf(a2, w2, acc);
                acc = fmaf(b0, w3, acc);
                acc = fmaf(b1, w4, acc);
                acc = fmaf(b2, w5, acc);
                acc = fmaf(c0, w6, acc);
                acc = fmaf(c1, w7, acc);
                acc = fmaf(c2, w8, acc);
                const float v = fmaxf(fmaf(acc + bias, scale, shift), 0.0f);
                vals[r] = v;
                mx = fmaxf(mx, v);       // v >= 0, no fabs needed
                a0 = b0; a1 = b1; a2 = b2;
                b0 = c0; b1 = c1; b2 = c2;
            }
        }
    }

    const float bmax = block_max_256(mx);
    const int survive = (bmax >= DW_THRESH) ? 1 : 0;
    if (tid == 0) g_flag[map] = survive;

    if (survive && colok) {
        float* yout = g_y + (size_t)map * HWOUT + col;
        #pragma unroll
        for (int r = 0; r < 14; r++)
            if (r < nrows) yout[(row0 + r) * WOUT] = vals[r];
    }
}

// ---------------------------------------------------------------------------
// Kernel M: deterministic per-batch survivor compaction (1 warp per batch).
// ---------------------------------------------------------------------------
__global__ void compact_kernel()
{
    const int b = blockIdx.x;
    const int lane = threadIdx.x;
    int base = 0;
    #pragma unroll
    for (int it = 0; it < CIN / 32; it++) {
        const int ch = it * 32 + lane;
        const int f = g_flag[b * CIN + ch];
        const unsigned m = __ballot_sync(0xffffffffu, f != 0);
        if (f) {
            const int pos = base + __popc(m & ((1u << lane) - 1u));
            g_list[b * CIN + pos] = (short)ch;
        }
        base += __popc(m);
    }
    if (lane == 0) g_cnt[b] = base;
}

// ---------------------------------------------------------------------------
// Kernel B: pointwise GEMM + bias + BN + ReLU + cut.
// One 256-thread block per (b,o) map. cnt==0 fast path: uniform float4 fill.
// ---------------------------------------------------------------------------
__global__ __launch_bounds__(256, 8)
void pw_kernel(const float* __restrict__ pw_w,
               const float* __restrict__ pw_b,
               const float* __restrict__ pw_gamma,
               const float* __restrict__ pw_beta,
               const float* __restrict__ pw_mean,
               const float* __restrict__ pw_var,
               float* __restrict__ out)
{
    const int bo  = blockIdx.x;            // b * COUT + o
    const int o   = bo & (COUT - 1);
    const int bi  = bo >> 9;               // COUT = 512
    const int tid = threadIdx.x;

    const int cnt = g_cnt[bi];

    const float scale = pw_gamma[o] * rsqrtf(pw_var[o] + EPS);
    const float shift = pw_beta[o] - pw_mean[o] * scale;
    const float bias  = pw_b[o];

    float4* op4 = (float4*)(out + (size_t)bo * HWOUT);

    if (cnt == 0) {
        // All input maps zero: z is uniform relu(bias*scale+shift); cut if < thresh.
        float v = fmaxf(fmaf(bias, scale, shift), 0.0f);
        if (v < PW_THRESH) v = 0.0f;
        const float4 val = make_float4(v, v, v, v);
        #pragma unroll
        for (int r = 0; r < 3; r++) {
            const int idx = tid + r * 256;
            if (idx < HWOUT / 4) op4[idx] = val;     // 729 float4
        }
        return;
    }

    // ---- survivor path (rare): vectorized channel GEMM over compacted list ----
    __shared__ float wrow[CIN];
    __shared__ short lst[CIN];
    wrow[tid] = pw_w[(size_t)o * CIN + tid];
    lst[tid]  = g_list[bi * CIN + tid];
    __syncthreads();

    float4 acc[3];
    #pragma unroll
    for (int r = 0; r < 3; r++) acc[r] = make_float4(0.f, 0.f, 0.f, 0.f);

    for (int k = 0; k < cnt; k++) {
        const int ch = lst[k];
        const float wv = wrow[ch];
        const float4* yr4 = (const float4*)(g_y + ((size_t)bi * CIN + ch) * HWOUT);
        #pragma unroll
        for (int r = 0; r < 3; r++) {
            const int idx = tid + r * 256;
            if (idx < HWOUT / 4) {
                const float4 yv = yr4[idx];
                acc[r].x = fmaf(yv.x, wv, acc[r].x);
                acc[r].y = fmaf(yv.y, wv, acc[r].y);
                acc[r].z = fmaf(yv.z, wv, acc[r].z);
                acc[r].w = fmaf(yv.w, wv, acc[r].w);
            }
        }
    }

    float4 z[3];
    float mx = 0.0f;
    #pragma unroll
    for (int r = 0; r < 3; r++) {
        z[r].x = fmaxf(fmaf(acc[r].x + bias, scale, shift), 0.0f);
        z[r].y = fmaxf(fmaf(acc[r].y + bias, scale, shift), 0.0f);
        z[r].z = fmaxf(fmaf(acc[r].z + bias, scale, shift), 0.0f);
        z[r].w = fmaxf(fmaf(acc[r].w + bias, scale, shift), 0.0f);
        mx = fmaxf(mx, fmaxf(fmaxf(z[r].x, z[r].y), fmaxf(z[r].z, z[r].w)));
    }

    const float bmax = block_max_256(mx);
    const bool cut = (bmax < PW_THRESH);

    #pragma unroll
    for (int r = 0; r < 3; r++) {
        const int idx = tid + r * 256;
        if (idx < HWOUT / 4)
            op4[idx] = cut ? make_float4(0.f, 0.f, 0.f, 0.f) : z[r];
    }
}

// ---------------------------------------------------------------------------
extern "C" void kernel_launch(void* const* d_in, const int* in_sizes, int n_in,
                              void* d_out, int out_size)
{
    const float* x        = (const float*)d_in[0];
    const float* dw_w     = (const float*)d_in[1];
    const float* dw_b     = (const float*)d_in[2];
    const float* dw_gamma = (const float*)d_in[3];
    const float* dw_beta  = (const float*)d_in[4];
    const float* dw_mean  = (const float*)d_in[5];
    const float* dw_var   = (const float*)d_in[6];
    const float* pw_w     = (const float*)d_in[7];
    const float* pw_b     = (const float*)d_in[8];
    const float* pw_gamma = (const float*)d_in[9];
    const float* pw_beta  = (const float*)d_in[10];
    const float* pw_mean  = (const float*)d_in[11];
    const float* pw_var   = (const float*)d_in[12];
    float* out = (float*)d_out;

    dw_kernel<<<B_ * CIN, 256>>>(x, dw_w, dw_b, dw_gamma, dw_beta, dw_mean, dw_var);
    compact_kernel<<<B_, 32>>>();
    pw_kernel<<<B_ * COUT, 256>>>(pw_w, pw_b, pw_gamma, pw_beta, pw_mean, pw_var, out);
}

// round 4
// speedup vs baseline: 5.7314x; 1.0385x over previous
#include <cuda_runtime.h>
#include <cstdint>

#define B_    32
#define CIN   256
#define COUT  512
#define HIN   56
#define WIN   56
#define HOUT  54
#define WOUT  54
#define HWOUT (HOUT * WOUT)          // 2916 = 729 * 4
#define EPS   1e-5f
#define DW_THRESH 4.0f
#define PW_THRESH 0.001f

// Scratch (device globals: the only allowed scratch mechanism).
__device__ float g_y[(size_t)B_ * CIN * HWOUT];   // depthwise output, written only for survivors
__device__ int   g_flag[B_ * CIN];                // per-(b,c) survival flag
__device__ int   g_cnt[B_];                       // survivors per batch
__device__ short g_list[B_ * CIN];                // compacted ascending channel list per batch

__device__ __forceinline__ float block_max_256(float v) {
    __shared__ float s_red[8];
    #pragma unroll
    for (int off = 16; off > 0; off >>= 1)
        v = fmaxf(v, __shfl_down_sync(0xffffffffu, v, off));
    if ((threadIdx.x & 31) == 0) s_red[threadIdx.x >> 5] = v;
    __syncthreads();
    if (threadIdx.x < 8) {
        v = s_red[threadIdx.x];
        #pragma unroll
        for (int off = 4; off > 0; off >>= 1)
            v = fmaxf(v, __shfl_down_sync(0xffu, v, off));
        if (threadIdx.x == 0) s_red[0] = v;
    }
    __syncthreads();
    float r = s_red[0];
    __syncthreads();
    return r;
}

// ---------------------------------------------------------------------------
// Kernel A: depthwise 3x3 VALID + bias + BN + ReLU + map-max + cut flag.
// One 256-thread block per (b,c) map. Each thread owns a PAIR of adjacent
// output columns (2 float2 LDS per input row serve 2 outputs) and 7 output
// rows with a rolling 3-row register window.
// ---------------------------------------------------------------------------
__global__ __launch_bounds__(256, 8)
void dw_kernel(const float* __restrict__ x,
               const float* __restrict__ dw_w,
               const float* __restrict__ dw_b,
               const float* __restrict__ dw_gamma,
               const float* __restrict__ dw_beta,
               const float* __restrict__ dw_mean,
               const float* __restrict__ dw_var)
{
    const int map = blockIdx.x;            // b * CIN + c
    const int c   = map & (CIN - 1);
    const int tid = threadIdx.x;

    __shared__ float tile[HIN * WIN];      // 12.25 KB
    __shared__ float wsh[9];

    // Vectorized tile load: 3136 floats = 784 float4
    {
        const float4* xin4 = (const float4*)(x + (size_t)map * (HIN * WIN));
        float4* t4 = (float4*)tile;
        #pragma unroll
        for (int r = 0; r < 4; r++) {
            const int i = tid + r * 256;
            if (i < (HIN * WIN) / 4) t4[i] = xin4[i];
        }
    }
    if (tid < 9) wsh[tid] = dw_w[c * 9 + tid];
    __syncthreads();

    const float w0 = wsh[0], w1 = wsh[1], w2 = wsh[2];
    const float w3 = wsh[3], w4 = wsh[4], w5 = wsh[5];
    const float w6 = wsh[6], w7 = wsh[7], w8 = wsh[8];

    const float scale = dw_gamma[c] * rsqrtf(dw_var[c] + EPS);
    const float shift = dw_beta[c] - dw_mean[c] * scale;
    const float bias  = dw_b[c];

    // Thread layout: 32 lanes -> column pairs (27 valid), 8 groups -> row strips.
    const int cp    = tid & 31;            // column pair index, valid < 27
    const int grp   = tid >> 5;            // 0..7
    const int row0  = grp * 7;             // output rows [row0, row0+nrows)
    const int nrows = (grp == 7) ? 5 : 7;  // 7*7 + 5 = 54
    const int col   = 2 * cp;              // first output column of pair
    const bool colok = (cp < 27);

    float vL[7], vR[7];
    float mx = 0.0f;

    if (colok) {
        // Rolling window: 3 input rows x 4 values (two float2 loads per row).
        const float2* prow = (const float2*)(tile + row0 * WIN + col); // 8B aligned
        // rows row0, row0+1
        float2 aL = prow[0], aR = prow[1]; prow += WIN / 2;
        float2 bL = prow[0], bR = prow[1]; prow += WIN / 2;
        #pragma unroll
        for (int r = 0; r < 7; r++) {
            if (r < nrows) {
                const float2 cL = prow[0], cR = prow[1]; prow += WIN / 2;
                // left output uses cols {0,1,2}; right uses {1,2,3}
                float accL = aL.x * w0, accR = aL.y * w0;
                accL = fmaf(aL.y, w1, accL);  accR = fmaf(aR.x, w1, accR);
                accL = fmaf(aR.x, w2, accL);  accR = fmaf(aR.y, w2, accR);
                accL = fmaf(bL.x, w3, accL);  accR = fmaf(bL.y, w3, accR);
                accL = fmaf(bL.y, w4, accL);  accR = fmaf(bR.x, w4, accR);
                accL = fmaf(bR.x, w5, accL);  accR = fmaf(bR.y, w5, accR);
                accL = fmaf(cL.x, w6, accL);  accR = fmaf(cL.y, w6, accR);
                accL = fmaf(cL.y, w7, accL);  accR = fmaf(cR.x, w7, accR);
                accL = fmaf(cR.x, w8, accL);  accR = fmaf(cR.y, w8, accR);
                const float zL = fmaxf(fmaf(accL + bias, scale, shift), 0.0f);
                const float zR = fmaxf(fmaf(accR + bias, scale, shift), 0.0f);
                vL[r] = zL; vR[r] = zR;
                mx = fmaxf(mx, fmaxf(zL, zR));     // z >= 0
                aL = bL; aR = bR;
                bL = cL; bR = cR;
            }
        }
    }

    const float bmax = block_max_256(mx);
    const int survive = (bmax >= DW_THRESH) ? 1 : 0;
    if (tid == 0) g_flag[map] = survive;

    if (survive && colok) {
        float* yout = g_y + (size_t)map * HWOUT + col;
        #pragma unroll
        for (int r = 0; r < 7; r++)
            if (r < nrows)
                *(float2*)(yout + (row0 + r) * WOUT) = make_float2(vL[r], vR[r]);
    }
}

// ---------------------------------------------------------------------------
// Kernel M: deterministic per-batch survivor compaction (1 warp per batch).
// ---------------------------------------------------------------------------
__global__ void compact_kernel()
{
    const int b = blockIdx.x;
    const int lane = threadIdx.x;
    int base = 0;
    #pragma unroll
    for (int it = 0; it < CIN / 32; it++) {
        const int ch = it * 32 + lane;
        const int f = g_flag[b * CIN + ch];
        const unsigned m = __ballot_sync(0xffffffffu, f != 0);
        if (f) {
            const int pos = base + __popc(m & ((1u << lane) - 1u));
            g_list[b * CIN + pos] = (short)ch;
        }
        base += __popc(m);
    }
    if (lane == 0) g_cnt[b] = base;
}

// ---------------------------------------------------------------------------
// Kernel B: pointwise GEMM + bias + BN + ReLU + cut.
// One 256-thread block per (b,o) map. cnt==0 fast path: uniform float4 fill.
// ---------------------------------------------------------------------------
__global__ __launch_bounds__(256, 8)
void pw_kernel(const float* __restrict__ pw_w,
               const float* __restrict__ pw_b,
               const float* __restrict__ pw_gamma,
               const float* __restrict__ pw_beta,
               const float* __restrict__ pw_mean,
               const float* __restrict__ pw_var,
               float* __restrict__ out)
{
    const int bo  = blockIdx.x;            // b * COUT + o
    const int o   = bo & (COUT - 1);
    const int bi  = bo >> 9;               // COUT = 512
    const int tid = threadIdx.x;

    const int cnt = g_cnt[bi];

    const float scale = pw_gamma[o] * rsqrtf(pw_var[o] + EPS);
    const float shift = pw_beta[o] - pw_mean[o] * scale;
    const float bias  = pw_b[o];

    float4* op4 = (float4*)(out + (size_t)bo * HWOUT);

    if (cnt == 0) {
        // All input maps zero: z is uniform relu(bias*scale+shift); cut if < thresh.
        float v = fmaxf(fmaf(bias, scale, shift), 0.0f);
        if (v < PW_THRESH) v = 0.0f;
        const float4 val = make_float4(v, v, v, v);
        #pragma unroll
        for (int r = 0; r < 3; r++) {
            const int idx = tid + r * 256;
            if (idx < HWOUT / 4) op4[idx] = val;     // 729 float4
        }
        return;
    }

    // ---- survivor path (rare): vectorized channel GEMM over compacted list ----
    __shared__ float wrow[CIN];
    __shared__ short lst[CIN];
    wrow[tid] = pw_w[(size_t)o * CIN + tid];
    lst[tid]  = g_list[bi * CIN + tid];
    __syncthreads();

    float4 acc[3];
    #pragma unroll
    for (int r = 0; r < 3; r++) acc[r] = make_float4(0.f, 0.f, 0.f, 0.f);

    for (int k = 0; k < cnt; k++) {
        const int ch = lst[k];
        const float wv = wrow[ch];
        const float4* yr4 = (const float4*)(g_y + ((size_t)bi * CIN + ch) * HWOUT);
        #pragma unroll
        for (int r = 0; r < 3; r++) {
            const int idx = tid + r * 256;
            if (idx < HWOUT / 4) {
                const float4 yv = yr4[idx];
                acc[r].x = fmaf(yv.x, wv, acc[r].x);
                acc[r].y = fmaf(yv.y, wv, acc[r].y);
                acc[r].z = fmaf(yv.z, wv, acc[r].z);
                acc[r].w = fmaf(yv.w, wv, acc[r].w);
            }
        }
    }

    float4 z[3];
    float mx = 0.0f;
    #pragma unroll
    for (int r = 0; r < 3; r++) {
        z[r].x = fmaxf(fmaf(acc[r].x + bias, scale, shift), 0.0f);
        z[r].y = fmaxf(fmaf(acc[r].y + bias, scale, shift), 0.0f);
        z[r].z = fmaxf(fmaf(acc[r].z + bias, scale, shift), 0.0f);
        z[r].w = fmaxf(fmaf(acc[r].w + bias, scale, shift), 0.0f);
        mx = fmaxf(mx, fmaxf(fmaxf(z[r].x, z[r].y), fmaxf(z[r].z, z[r].w)));
    }

    const float bmax = block_max_256(mx);
    const bool cut = (bmax < PW_THRESH);

    #pragma unroll
    for (int r = 0; r < 3; r++) {
        const int idx = tid + r * 256;
        if (idx < HWOUT / 4)
            op4[idx] = cut ? make_float4(0.f, 0.f, 0.f, 0.f) : z[r];
    }
}

// ---------------------------------------------------------------------------
extern "C" void kernel_launch(void* const* d_in, const int* in_sizes, int n_in,
                              void* d_out, int out_size)
{
    const float* x        = (const float*)d_in[0];
    const float* dw_w     = (const float*)d_in[1];
    const float* dw_b     = (const float*)d_in[2];
    const float* dw_gamma = (const float*)d_in[3];
    const float* dw_beta  = (const float*)d_in[4];
    const float* dw_mean  = (const float*)d_in[5];
    const float* dw_var   = (const float*)d_in[6];
    const float* pw_w     = (const float*)d_in[7];
    const float* pw_b     = (const float*)d_in[8];
    const float* pw_gamma = (const float*)d_in[9];
    const float* pw_beta  = (const float*)d_in[10];
    const float* pw_mean  = (const float*)d_in[11];
    const float* pw_var   = (const float*)d_in[12];
    float* out = (float*)d_out;

    dw_kernel<<<B_ * CIN, 256>>>(x, dw_w, dw_b, dw_gamma, dw_beta, dw_mean, dw_var);
    compact_kernel<<<B_, 32>>>();
    pw_kernel<<<B_ * COUT, 256>>>(pw_w, pw_b, pw_gamma, pw_beta, pw_mean, pw_var, out);
}